// round 2
// baseline (speedup 1.0000x reference)
#include <cuda_runtime.h>

#define NN 8192      // nodes
#define HD 128       // hidden dim
#define EE 16384     // edges
#define EDF 16       // edge feature dim
#define MH 64        // mlp hidden
#define KC2 8320     // (MH+1)*HD columns of U (65th k-row carries b2)

// ---- scratch (static __device__, allocation-guard safe) ----
__device__ float g_W2g[HD * KC2];           // [j][col], col = k*128+i   (~4.26MB)
__device__ float g_hid[EE * MH];            // relu(ef@W1+b1)            (4MB)
__device__ float g_m[NN * HD];              // scatter accumulator       (4MB)
__device__ float g_U[(size_t)NN * KC2];     // per-node transformed      (~273MB)

// ---------------------------------------------------------------------------
// prep: rearrange W2 [64,16384] (+ b2 as 65th k-row) into g_W2g[j][k*128+i],
//       and zero the message accumulator.
// ---------------------------------------------------------------------------
__global__ void prep_kernel(const float* __restrict__ W2, const float* __restrict__ b2) {
    int idx = blockIdx.x * blockDim.x + threadIdx.x;
    const int TW2 = MH * HD * HD;           // 1048576
    if (idx < TW2) {
        int k = idx >> 14;                  // /(HD*HD)
        int r = idx & 16383;
        int i = r >> 7;
        int j = r & 127;
        g_W2g[j * KC2 + (k << 7) + i] = W2[idx];
    } else if (idx < TW2 + HD * HD) {
        int r = idx - TW2;
        int i = r >> 7;
        int j = r & 127;
        g_W2g[j * KC2 + (MH << 7) + i] = b2[(i << 7) + j];
    }
    if (idx < NN * HD) g_m[idx] = 0.0f;
}

// ---------------------------------------------------------------------------
// edge MLP hidden: g_hid[e,k] = relu(b1[k] + sum_t ef[e,t]*W1[t,k])
// ---------------------------------------------------------------------------
__global__ void hid_kernel(const float* __restrict__ ef, const float* __restrict__ W1,
                           const float* __restrict__ b1) {
    __shared__ float W1s[EDF * MH];
    __shared__ float b1s[MH];
    int tid = threadIdx.x;
    for (int i2 = tid; i2 < EDF * MH; i2 += blockDim.x) W1s[i2] = W1[i2];
    if (tid < MH) b1s[tid] = b1[tid];
    __syncthreads();
    int idx = blockIdx.x * blockDim.x + tid;    // e*64 + k
    int e = idx >> 6, k = idx & 63;
    float acc = b1s[k];
    const float* efe = ef + e * EDF;
    #pragma unroll
    for (int t = 0; t < EDF; t++) acc += efe[t] * W1s[t * MH + k];
    g_hid[idx] = fmaxf(acc, 0.0f);
}

// ---------------------------------------------------------------------------
// U[n][col] = sum_j h[n][j] * g_W2g[j][col]   (GEMM 8192 x 8320, K=128)
// Block: 64 node-rows x 128 cols. 128 threads, 8x8 register tile per thread.
// ---------------------------------------------------------------------------
__global__ __launch_bounds__(128) void u_kernel(const float* __restrict__ hin) {
    __shared__ float A_s[64][129];      // h tile (padded: conflict-free column reads)
    __shared__ float Ws[16 * 128];      // W2g K-chunk
    int tid = threadIdx.x;
    int n0 = blockIdx.x * 64;
    int colbase = blockIdx.y * 128;
    for (int p = 0; p < 64; p++)
        A_s[p][tid] = hin[(n0 + p) * HD + tid];
    __syncthreads();

    int ty = tid >> 4, tx = tid & 15;   // ty: 8 node-groups, tx: 16 col-groups
    float acc[8][8] = {};

    for (int c = 0; c < 8; c++) {       // K=128 in chunks of 16
        int jb = c * 16;
        if (c) __syncthreads();         // WAR on Ws
        const float4* B4 = reinterpret_cast<const float4*>(g_W2g);
        float4* Ws4 = reinterpret_cast<float4*>(Ws);
        #pragma unroll
        for (int p = 0; p < 4; p++) {
            int t4 = tid + p * 128;                 // 0..511
            int kk = t4 >> 5, c4 = t4 & 31;
            Ws4[t4] = B4[((jb + kk) * KC2 + colbase) / 4 + c4];
        }
        __syncthreads();
        #pragma unroll 8
        for (int kk = 0; kk < 16; kk++) {
            float xv[8], wv[8];
            #pragma unroll
            for (int a = 0; a < 8; a++) xv[a] = A_s[ty * 8 + a][jb + kk];
            float4 w0 = *reinterpret_cast<const float4*>(&Ws[kk * 128 + tx * 8]);
            float4 w1 = *reinterpret_cast<const float4*>(&Ws[kk * 128 + tx * 8 + 4]);
            wv[0] = w0.x; wv[1] = w0.y; wv[2] = w0.z; wv[3] = w0.w;
            wv[4] = w1.x; wv[5] = w1.y; wv[6] = w1.z; wv[7] = w1.w;
            #pragma unroll
            for (int a = 0; a < 8; a++)
                #pragma unroll
                for (int b = 0; b < 8; b++)
                    acc[a][b] += xv[a] * wv[b];
        }
    }
    #pragma unroll
    for (int a = 0; a < 8; a++) {
        size_t off = (size_t)(n0 + ty * 8 + a) * KC2 + colbase + tx * 8;
        float4 o0 = make_float4(acc[a][0], acc[a][1], acc[a][2], acc[a][3]);
        float4 o1 = make_float4(acc[a][4], acc[a][5], acc[a][6], acc[a][7]);
        *reinterpret_cast<float4*>(g_U + off) = o0;
        *reinterpret_cast<float4*>(g_U + off + 4) = o1;
    }
}

// ---------------------------------------------------------------------------
// messages[e,i] = sum_{k=0..64} hid_ext[e,k] * U[src[e]][k*128+i]
// scatter-added into g_m[tgt[e]] with atomics. 16 edges / block, 128 threads.
// ---------------------------------------------------------------------------
#define EB2 16
__global__ __launch_bounds__(128) void msg_kernel(const int* __restrict__ edge_index) {
    __shared__ float hid_s[EB2][66];
    __shared__ int s_src[EB2], s_tgt[EB2];
    int tid = threadIdx.x;
    int e_base = blockIdx.x * EB2;
    if (tid < EB2) {
        s_src[tid] = edge_index[e_base + tid];
        s_tgt[tid] = edge_index[EE + e_base + tid];
        hid_s[tid][64] = 1.0f;                      // bias row weight
    }
    for (int idx = tid; idx < EB2 * MH; idx += 128) {
        int e = idx >> 6, k = idx & 63;
        hid_s[e][k] = g_hid[(e_base + e) * MH + k];
    }
    __syncthreads();
    for (int e = 0; e < EB2; e++) {
        const float* Ur = g_U + (size_t)s_src[e] * KC2;
        float acc = 0.0f;
        #pragma unroll 5
        for (int k = 0; k < 65; k++)
            acc += hid_s[e][k] * Ur[(k << 7) + tid];
        atomicAdd(&g_m[s_tgt[e] * HD + tid], acc);
    }
}

// ---------------------------------------------------------------------------
// GRU cell: out = (1-z)*tanh(gi_n + r*gh_n) + z*h, gates from m and h.
// 16 nodes per block, 128 threads (thread = output channel i).
// ---------------------------------------------------------------------------
#define BN 16
__global__ __launch_bounds__(128) void gru_kernel(
        const float* __restrict__ hin,
        const float* __restrict__ W_ih, const float* __restrict__ W_hh,
        const float* __restrict__ b_ih, const float* __restrict__ b_hh,
        float* __restrict__ out) {
    __shared__ float m_s[BN][HD];
    __shared__ float h_s[BN][HD];
    int tid = threadIdx.x;
    int n0 = blockIdx.x * BN;
    for (int p = 0; p < BN; p++) {
        m_s[p][tid] = g_m[(n0 + p) * HD + tid];
        h_s[p][tid] = hin[(n0 + p) * HD + tid];
    }
    __syncthreads();
    int i = tid;
    float racc[BN], zacc[BN];
    float bir = b_ih[i] + b_hh[i];
    float biz = b_ih[HD + i] + b_hh[HD + i];
    #pragma unroll
    for (int e = 0; e < BN; e++) { racc[e] = bir; zacc[e] = biz; }
    const float* wir_p = W_ih + i * HD;
    const float* whr_p = W_hh + i * HD;
    const float* wiz_p = W_ih + (HD + i) * HD;
    const float* whz_p = W_hh + (HD + i) * HD;
    for (int j = 0; j < HD; j++) {
        float wir = wir_p[j], whr = whr_p[j], wiz = wiz_p[j], whz = whz_p[j];
        #pragma unroll
        for (int e = 0; e < BN; e++) {
            racc[e] += m_s[e][j] * wir + h_s[e][j] * whr;
            zacc[e] += m_s[e][j] * wiz + h_s[e][j] * whz;
        }
    }
    float ni[BN], nh[BN];
    float bin_ = b_ih[2 * HD + i];
    float bhn  = b_hh[2 * HD + i];
    #pragma unroll
    for (int e = 0; e < BN; e++) { ni[e] = bin_; nh[e] = bhn; }
    const float* win_p = W_ih + (2 * HD + i) * HD;
    const float* whn_p = W_hh + (2 * HD + i) * HD;
    for (int j = 0; j < HD; j++) {
        float win = win_p[j], whn = whn_p[j];
        #pragma unroll
        for (int e = 0; e < BN; e++) {
            ni[e] += m_s[e][j] * win;
            nh[e] += h_s[e][j] * whn;
        }
    }
    #pragma unroll
    for (int e = 0; e < BN; e++) {
        float r = 1.0f / (1.0f + expf(-racc[e]));
        float z = 1.0f / (1.0f + expf(-zacc[e]));
        float n = tanhf(ni[e] + r * nh[e]);
        out[(n0 + e) * HD + i] = (1.0f - z) * n + z * h_s[e][i];
    }
}

// ---------------------------------------------------------------------------
// metadata order: h, edge_index, edge_features, W1, b1, W2, b2,
//                 W_ih, W_hh, b_ih, b_hh ; output float32 [N, H]
// ---------------------------------------------------------------------------
extern "C" void kernel_launch(void* const* d_in, const int* in_sizes, int n_in,
                              void* d_out, int out_size) {
    const float* h_ptr      = (const float*)d_in[0];
    const int*   edge_index = (const int*)  d_in[1];
    const float* ef         = (const float*)d_in[2];
    const float* W1         = (const float*)d_in[3];
    const float* b1         = (const float*)d_in[4];
    const float* W2         = (const float*)d_in[5];
    const float* b2         = (const float*)d_in[6];
    const float* W_ih       = (const float*)d_in[7];
    const float* W_hh       = (const float*)d_in[8];
    const float* b_ih       = (const float*)d_in[9];
    const float* b_hh       = (const float*)d_in[10];
    float* out = (float*)d_out;

    prep_kernel<<<(MH * HD * HD + HD * HD + 255) / 256, 256>>>(W2, b2);
    hid_kernel<<<(EE * MH) / 256, 256>>>(ef, W1, b1);
    u_kernel<<<dim3(NN / 64, KC2 / 128), 128>>>(h_ptr);
    msg_kernel<<<EE / EB2, 128>>>(edge_index);
    gru_kernel<<<NN / BN, 128>>>(h_ptr, W_ih, W_hh, b_ih, b_hh, out);
}

// round 4
// speedup vs baseline: 1.6301x; 1.6301x over previous
#include <cuda_runtime.h>
#include <cstdint>

#define NN 8192      // nodes
#define HD 128       // hidden dim
#define EE 16384     // edges
#define EDF 16       // edge feature dim
#define MH 64        // mlp hidden
#define KC2 8320     // (MH+1)*HD columns of U (65th k-block carries b2)

// ---- scratch (static __device__, allocation-guard safe) ----
__device__ float g_hid[EE * MH];            // relu(ef@W1+b1)            (4MB)
__device__ float g_m[NN * HD];              // scatter accumulator       (4MB)
__device__ float g_U[(size_t)NN * KC2];     // per-node transformed      (~273MB)

// ===========================================================================
// helpers
// ===========================================================================
__device__ __forceinline__ float to_tf32(float x) {
    float y;
    asm("cvt.rna.tf32.f32 %0, %1;" : "=f"(y) : "f"(x));
    return y;
}
__device__ __forceinline__ void mma_tf32(float& c0, float& c1, float& c2, float& c3,
                                         uint32_t a0, uint32_t a1, uint32_t a2, uint32_t a3,
                                         uint32_t b0, uint32_t b1) {
    asm volatile(
        "mma.sync.aligned.m16n8k8.row.col.f32.tf32.tf32.f32 "
        "{%0,%1,%2,%3}, {%4,%5,%6,%7}, {%8,%9}, {%0,%1,%2,%3};"
        : "+f"(c0), "+f"(c1), "+f"(c2), "+f"(c3)
        : "r"(a0), "r"(a1), "r"(a2), "r"(a3), "r"(b0), "r"(b1));
}

// ===========================================================================
// hid_kernel: g_hid[e,k] = relu(b1[k] + sum_t ef[e,t]*W1[t,k]); also zeroes g_m
// (EE*MH == NN*HD == 1048576, one grid covers both)
// ===========================================================================
__global__ void hid_kernel(const float* __restrict__ ef, const float* __restrict__ W1,
                           const float* __restrict__ b1) {
    __shared__ float W1s[EDF * MH];
    __shared__ float b1s[MH];
    int tid = threadIdx.x;
    for (int i2 = tid; i2 < EDF * MH; i2 += blockDim.x) W1s[i2] = W1[i2];
    if (tid < MH) b1s[tid] = b1[tid];
    __syncthreads();
    int idx = blockIdx.x * blockDim.x + tid;    // e*64 + k
    int e = idx >> 6, k = idx & 63;
    float acc = b1s[k];
    const float* efe = ef + e * EDF;
    #pragma unroll
    for (int t = 0; t < EDF; t++) acc += efe[t] * W1s[t * MH + k];
    g_hid[idx] = fmaxf(acc, 0.0f);
    g_m[idx] = 0.0f;
}

// ===========================================================================
// u_mma_kernel: U[n][col] = sum_j h[n][j] * B[col][j], tf32 mma.sync.
//   B rows for colblock y<64 are W2 flat starting at W2 + y*16384;
//   colblock y==64 rows are b2 flat (bias as 65th k-block, weight 1 in msg).
// CTA: 128 rows x 128 cols x K=128. 512 threads = 16 warps (4 M x 4 N),
// warp tile 32x32 -> 2 m16-frags x 4 n8-frags, 16 K-chunks of 8.
// Dyn smem: A[128][132] + B[128][132] floats (tf32-rounded) = 132 KB.
// ===========================================================================
#define U_PAD 132
#define U_SMEM_BYTES (2 * 128 * U_PAD * 4)

__global__ __launch_bounds__(512) void u_mma_kernel(
        const float* __restrict__ hin, const float* __restrict__ W2,
        const float* __restrict__ b2) {
    extern __shared__ float smem[];
    float* A_s = smem;                  // [128][132]  row=m(node), col=k
    float* B_s = smem + 128 * U_PAD;    // [128][132]  row=n(col),  col=k

    int tid = threadIdx.x;
    int n0blk = blockIdx.x * 128;       // node base
    int colbase = blockIdx.y * 128;     // U column base

    // ---- global -> smem (tf32-rounded), coalesced float4 ----
    const float4* A4 = reinterpret_cast<const float4*>(hin + (size_t)n0blk * HD);
    const float*  Bsrc = (blockIdx.y < 64) ? (W2 + (size_t)blockIdx.y * 16384) : b2;
    const float4* B4 = reinterpret_cast<const float4*>(Bsrc);
    #pragma unroll
    for (int p = 0; p < 8; p++) {
        int idx4 = tid + p * 512;       // 0..4095
        int row = idx4 >> 5, c4 = idx4 & 31;
        float4 va = A4[idx4];
        float4 vb = B4[idx4];
        va.x = to_tf32(va.x); va.y = to_tf32(va.y);
        va.z = to_tf32(va.z); va.w = to_tf32(va.w);
        vb.x = to_tf32(vb.x); vb.y = to_tf32(vb.y);
        vb.z = to_tf32(vb.z); vb.w = to_tf32(vb.w);
        *reinterpret_cast<float4*>(&A_s[row * U_PAD + c4 * 4]) = va;
        *reinterpret_cast<float4*>(&B_s[row * U_PAD + c4 * 4]) = vb;
    }
    __syncthreads();

    int wid = tid >> 5, lane = tid & 31;
    int warp_m = (wid & 3) * 32;        // 4 M groups
    int warp_n = (wid >> 2) * 32;       // 4 N groups
    int g = lane >> 2, tg = lane & 3;   // groupID, thread-in-group

    float acc[2][4][4];
    #pragma unroll
    for (int mf = 0; mf < 2; mf++)
        #pragma unroll
        for (int nf = 0; nf < 4; nf++)
            #pragma unroll
            for (int q = 0; q < 4; q++) acc[mf][nf][q] = 0.0f;

    #pragma unroll
    for (int kc = 0; kc < 16; kc++) {
        int k0 = kc * 8;
        uint32_t a[2][4], b[4][2];
        #pragma unroll
        for (int mf = 0; mf < 2; mf++) {
            const float* ap = &A_s[(warp_m + mf * 16 + g) * U_PAD + k0 + tg];
            a[mf][0] = __float_as_uint(ap[0]);
            a[mf][1] = __float_as_uint(ap[8 * U_PAD]);
            a[mf][2] = __float_as_uint(ap[4]);
            a[mf][3] = __float_as_uint(ap[8 * U_PAD + 4]);
        }
        #pragma unroll
        for (int nf = 0; nf < 4; nf++) {
            const float* bp = &B_s[(warp_n + nf * 8 + g) * U_PAD + k0 + tg];
            b[nf][0] = __float_as_uint(bp[0]);
            b[nf][1] = __float_as_uint(bp[4]);
        }
        #pragma unroll
        for (int mf = 0; mf < 2; mf++)
            #pragma unroll
            for (int nf = 0; nf < 4; nf++)
                mma_tf32(acc[mf][nf][0], acc[mf][nf][1], acc[mf][nf][2], acc[mf][nf][3],
                         a[mf][0], a[mf][1], a[mf][2], a[mf][3],
                         b[nf][0], b[nf][1]);
    }

    // ---- epilogue: C frag (m16n8): c0/c1 row g col 2tg/2tg+1, c2/c3 row g+8 ----
    #pragma unroll
    for (int mf = 0; mf < 2; mf++) {
        int row = n0blk + warp_m + mf * 16 + g;
        #pragma unroll
        for (int nf = 0; nf < 4; nf++) {
            int col = colbase + warp_n + nf * 8 + 2 * tg;
            float* d0 = g_U + (size_t)row * KC2 + col;
            *reinterpret_cast<float2*>(d0) =
                make_float2(acc[mf][nf][0], acc[mf][nf][1]);
            *reinterpret_cast<float2*>(d0 + (size_t)8 * KC2) =
                make_float2(acc[mf][nf][2], acc[mf][nf][3]);
        }
    }
}

// ===========================================================================
// msg_kernel: one edge per block. messages[e,i] = sum_k hid[e,k]*U[src][k*128+i]
// + bias row (k=64, weight 1). Skips k where relu zeroed hid.
// ===========================================================================
__global__ __launch_bounds__(128) void msg_kernel(const int* __restrict__ edge_index) {
    __shared__ float hid_s[MH];
    __shared__ int ssrc, stgt;
    int e = blockIdx.x;
    int tid = threadIdx.x;
    if (tid < MH) hid_s[tid] = g_hid[e * MH + tid];
    if (tid == 0) { ssrc = edge_index[e]; stgt = edge_index[EE + e]; }
    __syncthreads();
    const float* Ur = g_U + (size_t)ssrc * KC2 + tid;
    float a0 = Ur[MH << 7];        // bias row (weight 1)
    float a1 = 0.f, a2 = 0.f, a3 = 0.f;
    #pragma unroll
    for (int k = 0; k < MH; k += 4) {
        float w0 = hid_s[k], w1 = hid_s[k + 1], w2 = hid_s[k + 2], w3 = hid_s[k + 3];
        if (w0 != 0.f) a0 += w0 * Ur[(k    ) << 7];
        if (w1 != 0.f) a1 += w1 * Ur[(k + 1) << 7];
        if (w2 != 0.f) a2 += w2 * Ur[(k + 2) << 7];
        if (w3 != 0.f) a3 += w3 * Ur[(k + 3) << 7];
    }
    atomicAdd(&g_m[stgt * HD + tid], (a0 + a1) + (a2 + a3));
}

// ===========================================================================
// GRU cell: out = (1-z)*tanh(gi_n + r*gh_n) + z*h
// ===========================================================================
#define BN 16
__global__ __launch_bounds__(128) void gru_kernel(
        const float* __restrict__ hin,
        const float* __restrict__ W_ih, const float* __restrict__ W_hh,
        const float* __restrict__ b_ih, const float* __restrict__ b_hh,
        float* __restrict__ out) {
    __shared__ float m_s[BN][HD];
    __shared__ float h_s[BN][HD];
    int tid = threadIdx.x;
    int n0 = blockIdx.x * BN;
    for (int p = 0; p < BN; p++) {
        m_s[p][tid] = g_m[(n0 + p) * HD + tid];
        h_s[p][tid] = hin[(n0 + p) * HD + tid];
    }
    __syncthreads();
    int i = tid;
    float racc[BN], zacc[BN];
    float bir = b_ih[i] + b_hh[i];
    float biz = b_ih[HD + i] + b_hh[HD + i];
    #pragma unroll
    for (int e = 0; e < BN; e++) { racc[e] = bir; zacc[e] = biz; }
    const float* wir_p = W_ih + i * HD;
    const float* whr_p = W_hh + i * HD;
    const float* wiz_p = W_ih + (HD + i) * HD;
    const float* whz_p = W_hh + (HD + i) * HD;
    for (int j = 0; j < HD; j++) {
        float wir = wir_p[j], whr = whr_p[j], wiz = wiz_p[j], whz = whz_p[j];
        #pragma unroll
        for (int e = 0; e < BN; e++) {
            racc[e] += m_s[e][j] * wir + h_s[e][j] * whr;
            zacc[e] += m_s[e][j] * wiz + h_s[e][j] * whz;
        }
    }
    float ni[BN], nh[BN];
    float bin_ = b_ih[2 * HD + i];
    float bhn  = b_hh[2 * HD + i];
    #pragma unroll
    for (int e = 0; e < BN; e++) { ni[e] = bin_; nh[e] = bhn; }
    const float* win_p = W_ih + (2 * HD + i) * HD;
    const float* whn_p = W_hh + (2 * HD + i) * HD;
    for (int j = 0; j < HD; j++) {
        float win = win_p[j], whn = whn_p[j];
        #pragma unroll
        for (int e = 0; e < BN; e++) {
            ni[e] += m_s[e][j] * win;
            nh[e] += h_s[e][j] * whn;
        }
    }
    #pragma unroll
    for (int e = 0; e < BN; e++) {
        float r = 1.0f / (1.0f + expf(-racc[e]));
        float z = 1.0f / (1.0f + expf(-zacc[e]));
        float n = tanhf(ni[e] + r * nh[e]);
        out[(n0 + e) * HD + i] = (1.0f - z) * n + z * h_s[e][i];
    }
}

// ===========================================================================
// metadata order: h, edge_index, edge_features, W1, b1, W2, b2,
//                 W_ih, W_hh, b_ih, b_hh ; output float32 [N, H]
// ===========================================================================
extern "C" void kernel_launch(void* const* d_in, const int* in_sizes, int n_in,
                              void* d_out, int out_size) {
    const float* h_ptr      = (const float*)d_in[0];
    const int*   edge_index = (const int*)  d_in[1];
    const float* ef         = (const float*)d_in[2];
    const float* W1         = (const float*)d_in[3];
    const float* b1         = (const float*)d_in[4];
    const float* W2         = (const float*)d_in[5];
    const float* b2         = (const float*)d_in[6];
    const float* W_ih       = (const float*)d_in[7];
    const float* W_hh       = (const float*)d_in[8];
    const float* b_ih       = (const float*)d_in[9];
    const float* b_hh       = (const float*)d_in[10];
    float* out = (float*)d_out;

    cudaFuncSetAttribute(u_mma_kernel, cudaFuncAttributeMaxDynamicSharedMemorySize,
                         U_SMEM_BYTES);

    hid_kernel<<<(EE * MH) / 256, 256>>>(ef, W1, b1);
    u_mma_kernel<<<dim3(NN / 128, KC2 / 128), 512, U_SMEM_BYTES>>>(h_ptr, W2, b2);
    msg_kernel<<<EE, 128>>>(edge_index);
    gru_kernel<<<NN / BN, 128>>>(h_ptr, W_ih, W_hh, b_ih, b_hh, out);
}

// round 5
// speedup vs baseline: 2.7299x; 1.6747x over previous
#include <cuda_runtime.h>
#include <cstdint>

#define NN 8192      // nodes
#define HD 128       // hidden dim
#define EE 16384     // edges
#define EDF 16       // edge feature dim
#define MH 64        // mlp hidden
#define KC2 8320     // (MH+1)*HD columns of U (65th k-block carries b2)
#define G3 384       // 3*HD gate columns

// ---- scratch (static __device__, allocation-guard safe) ----
__device__ float g_hid[EE * MH];            // relu(ef@W1+b1)            (4MB)
__device__ float g_m[NN * HD];              // scatter accumulator       (4MB)
__device__ float g_gi[NN * G3];             // m @ W_ih^T                (12.6MB)
__device__ float g_gh[NN * G3];             // h @ W_hh^T                (12.6MB)
__device__ float g_U[(size_t)NN * KC2];     // per-node transformed      (~273MB)

// ===========================================================================
// helpers
// ===========================================================================
__device__ __forceinline__ float to_tf32(float x) {
    float y;
    asm("cvt.rna.tf32.f32 %0, %1;" : "=f"(y) : "f"(x));
    return y;
}
__device__ __forceinline__ void mma_tf32(float& c0, float& c1, float& c2, float& c3,
                                         uint32_t a0, uint32_t a1, uint32_t a2, uint32_t a3,
                                         uint32_t b0, uint32_t b1) {
    asm volatile(
        "mma.sync.aligned.m16n8k8.row.col.f32.tf32.tf32.f32 "
        "{%0,%1,%2,%3}, {%4,%5,%6,%7}, {%8,%9}, {%0,%1,%2,%3};"
        : "+f"(c0), "+f"(c1), "+f"(c2), "+f"(c3)
        : "r"(a0), "r"(a1), "r"(a2), "r"(a3), "r"(b0), "r"(b1));
}

// ===========================================================================
// hid_kernel: g_hid[e,k] = relu(b1[k] + sum_t ef[e,t]*W1[t,k]); also zeroes g_m
// ===========================================================================
__global__ void hid_kernel(const float* __restrict__ ef, const float* __restrict__ W1,
                           const float* __restrict__ b1) {
    __shared__ float W1s[EDF * MH];
    __shared__ float b1s[MH];
    int tid = threadIdx.x;
    for (int i2 = tid; i2 < EDF * MH; i2 += blockDim.x) W1s[i2] = W1[i2];
    if (tid < MH) b1s[tid] = b1[tid];
    __syncthreads();
    int idx = blockIdx.x * blockDim.x + tid;    // e*64 + k
    int e = idx >> 6, k = idx & 63;
    float acc = b1s[k];
    const float* efe = ef + e * EDF;
    #pragma unroll
    for (int t = 0; t < EDF; t++) acc += efe[t] * W1s[t * MH + k];
    g_hid[idx] = fmaxf(acc, 0.0f);
    g_m[idx] = 0.0f;
}

// ===========================================================================
// u_mma_kernel: U[n][col] = sum_j h[n][j] * B[col][j], tf32 mma.sync.
// (unchanged from round 4 — preserves rel_err)
// ===========================================================================
#define U_PAD 132
#define U_SMEM_BYTES (2 * 128 * U_PAD * 4)

__global__ __launch_bounds__(512) void u_mma_kernel(
        const float* __restrict__ hin, const float* __restrict__ W2,
        const float* __restrict__ b2) {
    extern __shared__ float smem[];
    float* A_s = smem;                  // [128][132]  row=m(node), col=k
    float* B_s = smem + 128 * U_PAD;    // [128][132]  row=n(col),  col=k

    int tid = threadIdx.x;
    int n0blk = blockIdx.x * 128;       // node base
    int colbase = blockIdx.y * 128;     // U column base

    const float4* A4 = reinterpret_cast<const float4*>(hin + (size_t)n0blk * HD);
    const float*  Bsrc = (blockIdx.y < 64) ? (W2 + (size_t)blockIdx.y * 16384) : b2;
    const float4* B4 = reinterpret_cast<const float4*>(Bsrc);
    #pragma unroll
    for (int p = 0; p < 8; p++) {
        int idx4 = tid + p * 512;       // 0..4095
        int row = idx4 >> 5, c4 = idx4 & 31;
        float4 va = A4[idx4];
        float4 vb = B4[idx4];
        va.x = to_tf32(va.x); va.y = to_tf32(va.y);
        va.z = to_tf32(va.z); va.w = to_tf32(va.w);
        vb.x = to_tf32(vb.x); vb.y = to_tf32(vb.y);
        vb.z = to_tf32(vb.z); vb.w = to_tf32(vb.w);
        *reinterpret_cast<float4*>(&A_s[row * U_PAD + c4 * 4]) = va;
        *reinterpret_cast<float4*>(&B_s[row * U_PAD + c4 * 4]) = vb;
    }
    __syncthreads();

    int wid = tid >> 5, lane = tid & 31;
    int warp_m = (wid & 3) * 32;        // 4 M groups
    int warp_n = (wid >> 2) * 32;       // 4 N groups
    int g = lane >> 2, tg = lane & 3;   // groupID, thread-in-group

    float acc[2][4][4];
    #pragma unroll
    for (int mf = 0; mf < 2; mf++)
        #pragma unroll
        for (int nf = 0; nf < 4; nf++)
            #pragma unroll
            for (int q = 0; q < 4; q++) acc[mf][nf][q] = 0.0f;

    #pragma unroll
    for (int kc = 0; kc < 16; kc++) {
        int k0 = kc * 8;
        uint32_t a[2][4], b[4][2];
        #pragma unroll
        for (int mf = 0; mf < 2; mf++) {
            const float* ap = &A_s[(warp_m + mf * 16 + g) * U_PAD + k0 + tg];
            a[mf][0] = __float_as_uint(ap[0]);
            a[mf][1] = __float_as_uint(ap[8 * U_PAD]);
            a[mf][2] = __float_as_uint(ap[4]);
            a[mf][3] = __float_as_uint(ap[8 * U_PAD + 4]);
        }
        #pragma unroll
        for (int nf = 0; nf < 4; nf++) {
            const float* bp = &B_s[(warp_n + nf * 8 + g) * U_PAD + k0 + tg];
            b[nf][0] = __float_as_uint(bp[0]);
            b[nf][1] = __float_as_uint(bp[4]);
        }
        #pragma unroll
        for (int mf = 0; mf < 2; mf++)
            #pragma unroll
            for (int nf = 0; nf < 4; nf++)
                mma_tf32(acc[mf][nf][0], acc[mf][nf][1], acc[mf][nf][2], acc[mf][nf][3],
                         a[mf][0], a[mf][1], a[mf][2], a[mf][3],
                         b[nf][0], b[nf][1]);
    }

    #pragma unroll
    for (int mf = 0; mf < 2; mf++) {
        int row = n0blk + warp_m + mf * 16 + g;
        #pragma unroll
        for (int nf = 0; nf < 4; nf++) {
            int col = colbase + warp_n + nf * 8 + 2 * tg;
            float* d0 = g_U + (size_t)row * KC2 + col;
            *reinterpret_cast<float2*>(d0) =
                make_float2(acc[mf][nf][0], acc[mf][nf][1]);
            *reinterpret_cast<float2*>(d0 + (size_t)8 * KC2) =
                make_float2(acc[mf][nf][2], acc[mf][nf][3]);
        }
    }
}

// ===========================================================================
// msg_kernel: one edge per block (unchanged from round 4)
// ===========================================================================
__global__ __launch_bounds__(128) void msg_kernel(const int* __restrict__ edge_index) {
    __shared__ float hid_s[MH];
    __shared__ int ssrc, stgt;
    int e = blockIdx.x;
    int tid = threadIdx.x;
    if (tid < MH) hid_s[tid] = g_hid[e * MH + tid];
    if (tid == 0) { ssrc = edge_index[e]; stgt = edge_index[EE + e]; }
    __syncthreads();
    const float* Ur = g_U + (size_t)ssrc * KC2 + tid;
    float a0 = Ur[MH << 7];        // bias row (weight 1)
    float a1 = 0.f, a2 = 0.f, a3 = 0.f;
    #pragma unroll
    for (int k = 0; k < MH; k += 4) {
        float w0 = hid_s[k], w1 = hid_s[k + 1], w2 = hid_s[k + 2], w3 = hid_s[k + 3];
        if (w0 != 0.f) a0 += w0 * Ur[(k    ) << 7];
        if (w1 != 0.f) a1 += w1 * Ur[(k + 1) << 7];
        if (w2 != 0.f) a2 += w2 * Ur[(k + 2) << 7];
        if (w3 != 0.f) a3 += w3 * Ur[(k + 3) << 7];
    }
    atomicAdd(&g_m[stgt * HD + tid], (a0 + a1) + (a2 + a3));
}

// ===========================================================================
// gate_gemm: C[n, i] = sum_j A[n,j] * W[i,j]
//   z=0: A=g_m, W=W_ih -> g_gi ; z=1: A=h, W=W_hh -> g_gh
// Block: 64 nodes x 128 gate-cols, 128 threads, 8x8 register tile (fp32).
// All global reads coalesced; W transposed through smem.
// ===========================================================================
__global__ __launch_bounds__(128) void gate_gemm(
        const float* __restrict__ hin,
        const float* __restrict__ W_ih, const float* __restrict__ W_hh) {
    __shared__ float A_s[64][129];
    __shared__ float Ws[16 * 128];          // [kk][col]
    int tid = threadIdx.x;
    int n0 = blockIdx.x * 64;
    int colbase = blockIdx.y * 128;         // 0 / 128 / 256

    const float* A = blockIdx.z ? hin : (const float*)g_m;
    const float* W = blockIdx.z ? W_hh : W_ih;
    float* C = blockIdx.z ? g_gh : g_gi;

    for (int p = 0; p < 64; p++)
        A_s[p][tid] = A[(n0 + p) * HD + tid];
    __syncthreads();

    int ty = tid >> 4, tx = tid & 15;
    float acc[8][8] = {};

    for (int c = 0; c < 8; c++) {           // K=128 in chunks of 16
        int jb = c * 16;
        if (c) __syncthreads();             // WAR on Ws
        // transpose-load W chunk: Ws[kk][col] = W[(colbase+col)*128 + jb+kk]
        #pragma unroll
        for (int p = 0; p < 4; p++) {
            int idx4 = tid + p * 128;       // 0..511
            int col = idx4 >> 2, kq = (idx4 & 3) * 4;
            float4 w = *reinterpret_cast<const float4*>(&W[(colbase + col) * HD + jb + kq]);
            Ws[(kq + 0) * 128 + col] = w.x;
            Ws[(kq + 1) * 128 + col] = w.y;
            Ws[(kq + 2) * 128 + col] = w.z;
            Ws[(kq + 3) * 128 + col] = w.w;
        }
        __syncthreads();
        #pragma unroll 8
        for (int kk = 0; kk < 16; kk++) {
            float xv[8], wv[8];
            #pragma unroll
            for (int a = 0; a < 8; a++) xv[a] = A_s[ty * 8 + a][jb + kk];
            float4 w0 = *reinterpret_cast<const float4*>(&Ws[kk * 128 + tx * 8]);
            float4 w1 = *reinterpret_cast<const float4*>(&Ws[kk * 128 + tx * 8 + 4]);
            wv[0] = w0.x; wv[1] = w0.y; wv[2] = w0.z; wv[3] = w0.w;
            wv[4] = w1.x; wv[5] = w1.y; wv[6] = w1.z; wv[7] = w1.w;
            #pragma unroll
            for (int a = 0; a < 8; a++)
                #pragma unroll
                for (int b = 0; b < 8; b++)
                    acc[a][b] += xv[a] * wv[b];
        }
    }
    #pragma unroll
    for (int a = 0; a < 8; a++) {
        int off = (n0 + ty * 8 + a) * G3 + colbase + tx * 8;
        *reinterpret_cast<float4*>(C + off) =
            make_float4(acc[a][0], acc[a][1], acc[a][2], acc[a][3]);
        *reinterpret_cast<float4*>(C + off + 4) =
            make_float4(acc[a][4], acc[a][5], acc[a][6], acc[a][7]);
    }
}

// ===========================================================================
// gru_elem: fused gate nonlinearity + blend (coalesced, memory-bound)
// ===========================================================================
__global__ void gru_elem(const float* __restrict__ hin,
                         const float* __restrict__ b_ih, const float* __restrict__ b_hh,
                         float* __restrict__ out) {
    int idx = blockIdx.x * blockDim.x + threadIdx.x;    // n*128 + i
    int n = idx >> 7, i = idx & 127;
    const float* gi = g_gi + n * G3;
    const float* gh = g_gh + n * G3;
    float r = 1.0f / (1.0f + expf(-(gi[i] + b_ih[i] + gh[i] + b_hh[i])));
    float z = 1.0f / (1.0f + expf(-(gi[HD + i] + b_ih[HD + i] + gh[HD + i] + b_hh[HD + i])));
    float ng = tanhf(gi[2 * HD + i] + b_ih[2 * HD + i]
                     + r * (gh[2 * HD + i] + b_hh[2 * HD + i]));
    float hv = hin[idx];
    out[idx] = (1.0f - z) * ng + z * hv;
}

// ===========================================================================
// metadata order: h, edge_index, edge_features, W1, b1, W2, b2,
//                 W_ih, W_hh, b_ih, b_hh ; output float32 [N, H]
// ===========================================================================
extern "C" void kernel_launch(void* const* d_in, const int* in_sizes, int n_in,
                              void* d_out, int out_size) {
    const float* h_ptr      = (const float*)d_in[0];
    const int*   edge_index = (const int*)  d_in[1];
    const float* ef         = (const float*)d_in[2];
    const float* W1         = (const float*)d_in[3];
    const float* b1         = (const float*)d_in[4];
    const float* W2         = (const float*)d_in[5];
    const float* b2         = (const float*)d_in[6];
    const float* W_ih       = (const float*)d_in[7];
    const float* W_hh       = (const float*)d_in[8];
    const float* b_ih       = (const float*)d_in[9];
    const float* b_hh       = (const float*)d_in[10];
    float* out = (float*)d_out;

    cudaFuncSetAttribute(u_mma_kernel, cudaFuncAttributeMaxDynamicSharedMemorySize,
                         U_SMEM_BYTES);

    hid_kernel<<<(EE * MH) / 256, 256>>>(ef, W1, b1);
    u_mma_kernel<<<dim3(NN / 128, KC2 / 128), 512, U_SMEM_BYTES>>>(h_ptr, W2, b2);
    msg_kernel<<<EE, 128>>>(edge_index);
    gate_gemm<<<dim3(NN / 64, 3, 2), 128>>>(h_ptr, W_ih, W_hh);
    gru_elem<<<(NN * HD) / 256, 256>>>(h_ptr, b_ih, b_hh, out);
}